// round 1
// baseline (speedup 1.0000x reference)
#include <cuda_runtime.h>

// Problem constants
#define NVEC 65536      // 64*32*32 vectors
#define DIM  256        // embedding dim
#define KCB  4096       // codebook entries

// GEMM tiling
#define BN 128
#define BK 128
#define DC 32
#define TM 8
#define TK 8
// 256 threads = 16x16

#define LOSS_BLOCKS 1184

__device__ float  g_x2[NVEC];
__device__ float  g_e2[KCB];
__device__ int    g_idx[NVEC];
__device__ double g_part[LOSS_BLOCKS];

__device__ __forceinline__ unsigned fenc(float f) {
    unsigned u = __float_as_uint(f);
    return (u & 0x80000000u) ? ~u : (u | 0x80000000u);
}

// ---------------------------------------------------------------------------
// Row squared-norms: one warp per row, tree reduction (fp32, XLA-like order).
// which=0 -> g_x2, which=1 -> g_e2
// ---------------------------------------------------------------------------
__global__ void rownorm_kernel(const float* __restrict__ v, int rows, int which) {
    int row  = blockIdx.x * (blockDim.x >> 5) + (threadIdx.x >> 5);
    int lane = threadIdx.x & 31;
    if (row >= rows) return;
    const float4* p = reinterpret_cast<const float4*>(v + (size_t)row * DIM);
    float4 a = p[lane];
    float4 b = p[lane + 32];
    float s = ((a.x * a.x + a.y * a.y) + (a.z * a.z + a.w * a.w))
            + ((b.x * b.x + b.y * b.y) + (b.z * b.z + b.w * b.w));
    #pragma unroll
    for (int off = 16; off; off >>= 1)
        s += __shfl_xor_sync(0xffffffffu, s, off);
    if (lane == 0) {
        if (which) g_e2[row] = s;
        else       g_x2[row] = s;
    }
}

// ---------------------------------------------------------------------------
// Fused distance-GEMM + argmin. Each CTA: 128 rows x all 4096 codes.
// dist = (x2 + e2) - 2*dot  computed in fp32 (matches reference quantization),
// argmin tie-break = lowest index.
// ---------------------------------------------------------------------------
__global__ __launch_bounds__(256, 2)
void vq_argmin_kernel(const float* __restrict__ x, const float* __restrict__ cb) {
    // XOR-swizzled smem: phys(d,row) = d*128 + ((row>>2) ^ d)*4 + (row&3)
    __shared__ float xs[DC * BN];
    __shared__ float es[DC * BK];
    __shared__ unsigned long long red[BN];

    const int tid = threadIdx.x;
    const int tx  = tid & 15;
    const int ty  = tid >> 4;
    const int row0 = blockIdx.x * BN;

    float bestv[TM];
    int   besti[TM];
    #pragma unroll
    for (int i = 0; i < TM; i++) { bestv[i] = 3.4e38f; besti[i] = 0; }

    const int ld_d  = tid & 31;   // d within chunk
    const int ld_r0 = tid >> 5;   // base row 0..7

    const float* xbase = x + (size_t)row0 * DIM;

    for (int kt = 0; kt < KCB; kt += BK) {
        float acc[TM][TK];
        #pragma unroll
        for (int i = 0; i < TM; i++)
            #pragma unroll
            for (int j = 0; j < TK; j++) acc[i][j] = 0.f;

        const float* cbase = cb + (size_t)kt * DIM;

        for (int d0 = 0; d0 < DIM; d0 += DC) {
            __syncthreads();
            // Load 128x32 chunks of x and codebook into swizzled smem.
            // Warp = 32 consecutive d, same row -> coalesced LDG, conflict-free STS.
            #pragma unroll
            for (int i = 0; i < 16; i++) {
                int r = ld_r0 + i * 8;
                float vx = xbase[(size_t)r * DIM + d0 + ld_d];
                float ve = cbase[(size_t)r * DIM + d0 + ld_d];
                int c = ((r >> 2) ^ ld_d);
                int off = ld_d * 128 + (c << 2) + (r & 3);
                xs[off] = vx;
                es[off] = ve;
            }
            __syncthreads();

            #pragma unroll 4
            for (int d = 0; d < DC; d++) {
                float4 a0 = *reinterpret_cast<const float4*>(&xs[d * 128 + ((((ty << 1)    ) ^ d) << 2)]);
                float4 a1 = *reinterpret_cast<const float4*>(&xs[d * 128 + ((((ty << 1) + 1) ^ d) << 2)]);
                float4 b0 = *reinterpret_cast<const float4*>(&es[d * 128 + ((((tx << 1)    ) ^ d) << 2)]);
                float4 b1 = *reinterpret_cast<const float4*>(&es[d * 128 + ((((tx << 1) + 1) ^ d) << 2)]);
                float a[TM] = {a0.x, a0.y, a0.z, a0.w, a1.x, a1.y, a1.z, a1.w};
                float b[TK] = {b0.x, b0.y, b0.z, b0.w, b1.x, b1.y, b1.z, b1.w};
                #pragma unroll
                for (int i = 0; i < TM; i++)
                    #pragma unroll
                    for (int j = 0; j < TK; j++)
                        acc[i][j] = fmaf(a[i], b[j], acc[i][j]);
            }
        }

        // Epilogue: fp32-quantized distance, running argmin (strict < keeps lowest k)
        #pragma unroll
        for (int i = 0; i < TM; i++) {
            int r = ty * TM + i;
            float x2 = g_x2[row0 + r];
            #pragma unroll
            for (int j = 0; j < TK; j++) {
                int k = kt + tx * TK + j;
                float t = x2 + g_e2[k];
                float dist = t - 2.0f * acc[i][j];
                if (dist < bestv[i]) { bestv[i] = dist; besti[i] = k; }
            }
        }
    }

    // Cross-thread argmin: 64-bit key = (ordered float, idx); min => lowest idx on tie
    if (tid < BN) red[tid] = 0xFFFFFFFFFFFFFFFFull;
    __syncthreads();
    #pragma unroll
    for (int i = 0; i < TM; i++) {
        int r = ty * TM + i;
        unsigned long long key =
            ((unsigned long long)fenc(bestv[i]) << 32) | (unsigned)besti[i];
        atomicMin(&red[r], key);
    }
    __syncthreads();
    if (tid < BN) g_idx[row0 + tid] = (int)(red[tid] & 0xFFFFFFFFu);
}

// ---------------------------------------------------------------------------
// Gather + straight-through output + per-block loss partials (double accum).
// out[i] = x + (q - x)  (exact op order of the reference)
// ---------------------------------------------------------------------------
__global__ void vq_output_kernel(const float* __restrict__ x,
                                 const float* __restrict__ cb,
                                 float* __restrict__ out) {
    __shared__ double sred[256];
    double lsum = 0.0;
    const int nthreads = gridDim.x * blockDim.x;
    const int total4 = NVEC * DIM / 4;
    const float4* x4 = reinterpret_cast<const float4*>(x);
    float4* o4 = reinterpret_cast<float4*>(out);

    for (int i = blockIdx.x * blockDim.x + threadIdx.x; i < total4; i += nthreads) {
        int n = i >> 6;                 // 64 float4 per row
        int idx = g_idx[n];
        float4 q  = reinterpret_cast<const float4*>(cb + (size_t)idx * DIM)[i & 63];
        float4 xv = x4[i];
        float4 r;
        float d0 = q.x - xv.x; r.x = xv.x + d0; lsum += (double)(d0 * d0);
        float d1 = q.y - xv.y; r.y = xv.y + d1; lsum += (double)(d1 * d1);
        float d2 = q.z - xv.z; r.z = xv.z + d2; lsum += (double)(d2 * d2);
        float d3 = q.w - xv.w; r.w = xv.w + d3; lsum += (double)(d3 * d3);
        o4[i] = r;
    }
    sred[threadIdx.x] = lsum;
    __syncthreads();
    #pragma unroll
    for (int s = 128; s; s >>= 1) {
        if (threadIdx.x < s) sred[threadIdx.x] += sred[threadIdx.x + s];
        __syncthreads();
    }
    if (threadIdx.x == 0) g_part[blockIdx.x] = sred[0];
}

// ---------------------------------------------------------------------------
// Final loss reduction (deterministic fixed order) + tail fill
// ---------------------------------------------------------------------------
__global__ void loss_kernel(float* __restrict__ out, int out_size) {
    __shared__ double sred[256];
    double s = 0.0;
    for (int i = threadIdx.x; i < LOSS_BLOCKS; i += 256) s += g_part[i];
    sred[threadIdx.x] = s;
    __syncthreads();
    #pragma unroll
    for (int k = 128; k; k >>= 1) {
        if (threadIdx.x < k) sred[threadIdx.x] += sred[threadIdx.x + k];
        __syncthreads();
    }
    const int nq = NVEC * DIM;
    if (threadIdx.x == 0) {
        double m = sred[0] / (double)nq;
        float mf = (float)m;
        float loss = mf + 0.25f * mf;   // codebook_loss + 0.25*commitment (same value)
        if (out_size == nq + 1)      out[nq] = loss;
        else if (out_size == 1)      out[0] = loss;
        else if (out_size > nq)      out[out_size - 1] = loss;
    }
    // zero any padding gap (out is poisoned to 0xAA)
    for (int i = nq + 1 + threadIdx.x; i < out_size - 1; i += 256) out[i] = 0.f;
}

// ---------------------------------------------------------------------------
extern "C" void kernel_launch(void* const* d_in, const int* in_sizes, int n_in,
                              void* d_out, int out_size) {
    const float* x  = (const float*)d_in[0];
    const float* cb = (const float*)d_in[1];
    if (n_in >= 2 && in_sizes[0] == KCB * DIM && in_sizes[1] == NVEC * DIM) {
        // defensive: swapped input order
        const float* t = x; x = cb; cb = t;
    }
    float* out = (float*)d_out;

    rownorm_kernel<<<NVEC / 8, 256>>>(x,  NVEC, 0);
    rownorm_kernel<<<KCB  / 8, 256>>>(cb, KCB,  1);
    vq_argmin_kernel<<<NVEC / BN, 256>>>(x, cb);
    vq_output_kernel<<<LOSS_BLOCKS, 256>>>(x, cb, out);
    loss_kernel<<<1, 256>>>(out, out_size);
}